// round 12
// baseline (speedup 1.0000x reference)
#include <cuda_runtime.h>
#include <cuda_bf16.h>
#include <math.h>

#define N_NODES 50000
#define N_EDGES 800000
#define NFEAT   128
#define NHID    96
#define NCLASS  40
#define NODE_BLKS 196   // ceil(N_NODES/256)

// ---- static scratch (allocation-free) ----
__device__ __align__(16) float g_h[N_NODES * NHID];   // post-GEMM features
__device__ __align__(16) float g_a[N_NODES * NHID];   // post-aggregation features
__device__ int  g_cnt[N_NODES];     // degree histogram
__device__ int  g_cnt2[N_NODES];    // placement cursors
__device__ int  g_rowbeg[N_NODES];  // CSR segment base (atomic-claimed)
__device__ int  g_cursor;
__device__ __align__(16) int2 g_edges[N_EDGES];   // {src, bits(w)} compact

// ===========================================================================
// CSR build: zero -> hist -> scan+claim (1 kernel) -> place
// ===========================================================================
__global__ void zero_cnt_kernel() {
    int i = blockIdx.x * blockDim.x + threadIdx.x;
    if (i < N_NODES) { g_cnt[i] = 0; g_cnt2[i] = 0; }
    if (i == 0) g_cursor = 0;
}

__global__ void hist_kernel(const int* __restrict__ dst) {
    int e = blockIdx.x * blockDim.x + threadIdx.x;
    if (e < N_EDGES) atomicAdd(&g_cnt[dst[e]], 1);
}

// Block-local inclusive scan; block total claimed from global cursor.
__global__ void scan_claim_kernel() {
    __shared__ int sh[256];
    __shared__ int base_sh;
    int t = threadIdx.x;
    int i = blockIdx.x * 256 + t;
    int c = (i < N_NODES) ? g_cnt[i] : 0;
    sh[t] = c;
    __syncthreads();
#pragma unroll
    for (int off = 1; off < 256; off <<= 1) {
        int v = (t >= off) ? sh[t - off] : 0;
        __syncthreads();
        sh[t] += v;
        __syncthreads();
    }
    if (t == 255) base_sh = atomicAdd(&g_cursor, sh[255]);
    __syncthreads();
    if (i < N_NODES) g_rowbeg[i] = base_sh + sh[t] - c;
}

__global__ void place_kernel(const int* __restrict__ src,
                             const int* __restrict__ dst,
                             const float* __restrict__ ew) {
    int e = blockIdx.x * blockDim.x + threadIdx.x;
    if (e >= N_EDGES) return;
    int d = dst[e];
    int p = g_rowbeg[d] + atomicAdd(&g_cnt2[d], 1);
    g_edges[p] = make_int2(src[e], __float_as_int(ew[e]));
}

// ===========================================================================
// GEMM: g_h[r,c] = sum_k X[r,k]*W[k,c]. CTA tile 64x96, 256 threads (16x16),
// per-thread tile 4 rows x 6 cols (12 f32x2 accumulators, ~55 regs).
// __launch_bounds__(256,4): 4 CTAs/SM -> 32 warps (50% occ). R11 showed the
// GEMM still LDS-latency bound at 27% occ; warp supply is the lever.
// ===========================================================================
template <int K>
__global__ void __launch_bounds__(256, 4) gemm_kernel(const float* __restrict__ X,
                                                      const float* __restrict__ W) {
    __shared__ float Xs[32][68];    // [k][row], 64 rows + pad
    __shared__ float Ws[32][96];    // [k][col]
    int tx = threadIdx.x;           // 0..15 -> cols tx*6..tx*6+5
    int ty = threadIdx.y;           // 0..15 -> rows ty*4..ty*4+3
    int tid = ty * 16 + tx;
    int rowBase = blockIdx.x * 64;

    // acc2[i][p] = packed {col tx*6+2p, col tx*6+2p+1} for row ty*4+i
    unsigned long long acc2[4][3] = {};

    for (int kt = 0; kt < K; kt += 32) {
        // X tile: 64 rows x 8 float4 along K (transposed into Xs), 2 per thread
        for (int idx = tid; idx < 64 * 8; idx += 256) {
            int row = idx >> 3;
            int kc  = idx & 7;
            int gr = rowBase + row;
            if (gr >= N_NODES) gr = N_NODES - 1;
            float4 v = *reinterpret_cast<const float4*>(X + (size_t)gr * K + kt + kc * 4);
            Xs[kc * 4 + 0][row] = v.x;
            Xs[kc * 4 + 1][row] = v.y;
            Xs[kc * 4 + 2][row] = v.z;
            Xs[kc * 4 + 3][row] = v.w;
        }
        // W tile: 32 x 96, 3 float4 per thread
        for (int idx = tid; idx < 32 * 24; idx += 256) {
            int kk = idx / 24;
            int cc = idx % 24;
            *reinterpret_cast<float4*>(&Ws[kk][cc * 4]) =
                *reinterpret_cast<const float4*>(W + (size_t)(kt + kk) * NHID + cc * 4);
        }
        __syncthreads();

#pragma unroll
        for (int k = 0; k < 32; k++) {
            float xr[4];
            *reinterpret_cast<float4*>(&xr[0]) = *reinterpret_cast<float4*>(&Xs[k][ty * 4]);
            // 6 weight cols as 3 packed f32x2 (8B-aligned: byte offset 24*tx)
            unsigned long long wc2[3];
            wc2[0] = *reinterpret_cast<unsigned long long*>(&Ws[k][tx * 6]);
            wc2[1] = *reinterpret_cast<unsigned long long*>(&Ws[k][tx * 6 + 2]);
            wc2[2] = *reinterpret_cast<unsigned long long*>(&Ws[k][tx * 6 + 4]);
#pragma unroll
            for (int i = 0; i < 4; i++) {
                unsigned int xb = __float_as_uint(xr[i]);
                unsigned long long xs;
                asm("mov.b64 %0, {%1, %1};" : "=l"(xs) : "r"(xb));
#pragma unroll
                for (int p = 0; p < 3; p++)
                    asm("fma.rn.f32x2 %0, %1, %2, %0;"
                        : "+l"(acc2[i][p]) : "l"(xs), "l"(wc2[p]));
            }
        }
        __syncthreads();
    }

#pragma unroll
    for (int i = 0; i < 4; i++) {
        int gr = rowBase + ty * 4 + i;
        if (gr < N_NODES) {
            unsigned long long* o =
                reinterpret_cast<unsigned long long*>(g_h + (size_t)gr * NHID + tx * 6);
            o[0] = acc2[i][0];
            o[1] = acc2[i][1];
            o[2] = acc2[i][2];
        }
    }
}

// ===========================================================================
// Aggregation core: warp accumulates weighted rows of g_h for one node.
// 8-edge groups; tail done as one predicated 8-wide group (w=0 lanes).
// ===========================================================================
__device__ __forceinline__ void agg8(const int2* __restrict__ eb, int j, int cnt,
                                     bool full, int lane,
                                     float& a0, float& a1, float& a2) {
    int   srcs[8];
    float ws[8];
#pragma unroll
    for (int k = 0; k < 8; k++) {
        bool ok = full || (j + k < cnt);
        int2 e = ok ? __ldg(&eb[j + k]) : make_int2(0, 0);
        srcs[k] = e.x;
        ws[k]   = ok ? __int_as_float(e.y) : 0.f;
    }
    float v0[8], v1[8], v2[8];
#pragma unroll
    for (int k = 0; k < 8; k++) {
        const float* h = g_h + (size_t)srcs[k] * NHID;
        v0[k] = __ldg(h + lane);
        v1[k] = __ldg(h + lane + 32);
        v2[k] = __ldg(h + lane + 64);
    }
#pragma unroll
    for (int k = 0; k < 8; k++) {
        a0 += ws[k] * v0[k];
        a1 += ws[k] * v1[k];
        a2 += ws[k] * v2[k];
    }
}

__device__ __forceinline__ void agg_rows(int node, int lane,
                                         float& a0, float& a1, float& a2) {
    int beg = __ldg(&g_rowbeg[node]);
    int cnt = __ldg(&g_cnt[node]);
    const int2* eb = g_edges + beg;
    int nfull = cnt & ~7;
    for (int j = 0; j < nfull; j += 8)
        agg8(eb, j, cnt, true, lane, a0, a1, a2);
    if (cnt & 7)
        agg8(eb, nfull, cnt, false, lane, a0, a1, a2);
}

// Aggregation + bias + L2-normalize + ReLU. One warp per dst node.
__global__ void agg_kernel(const float* __restrict__ bias) {
    int gw   = (blockIdx.x * blockDim.x + threadIdx.x) >> 5;
    int lane = threadIdx.x & 31;
    if (gw >= N_NODES) return;

    float a0 = 0.f, a1 = 0.f, a2 = 0.f;
    agg_rows(gw, lane, a0, a1, a2);

    a0 += __ldg(bias + lane); a1 += __ldg(bias + lane + 32); a2 += __ldg(bias + lane + 64);
    float s = a0 * a0 + a1 * a1 + a2 * a2;
#pragma unroll
    for (int o = 16; o; o >>= 1) s += __shfl_xor_sync(0xFFFFFFFFu, s, o);
    float inv = 1.0f / fmaxf(sqrtf(s), 1e-12f);

    float* row = g_a + (size_t)gw * NHID;
    row[lane]      = fmaxf(a0 * inv, 0.f);
    row[lane + 32] = fmaxf(a1 * inv, 0.f);
    row[lane + 64] = fmaxf(a2 * inv, 0.f);
}

// ===========================================================================
// Layer 3 fused head: agg + bias + norm + relu + emb + logits + softmax.
// ===========================================================================
__global__ void agg_head_kernel(const float* __restrict__ bias,
                                const float* __restrict__ linW,
                                const float* __restrict__ linb,
                                float* __restrict__ out) {
    __shared__ float Ws[NHID * NCLASS];
    __shared__ float bs[NCLASS];
    __shared__ float esh[8][NHID];

    int tid = threadIdx.x;
    for (int i = tid; i < NHID * NCLASS; i += 256) Ws[i] = linW[i];
    if (tid < NCLASS) bs[tid] = linb[tid];
    __syncthreads();

    int wid  = tid >> 5;
    int lane = tid & 31;
    int node = blockIdx.x * 8 + wid;
    if (node >= N_NODES) return;

    float a0 = 0.f, a1 = 0.f, a2 = 0.f;
    agg_rows(node, lane, a0, a1, a2);

    a0 += __ldg(bias + lane); a1 += __ldg(bias + lane + 32); a2 += __ldg(bias + lane + 64);
    float s = a0 * a0 + a1 * a1 + a2 * a2;
#pragma unroll
    for (int o = 16; o; o >>= 1) s += __shfl_xor_sync(0xFFFFFFFFu, s, o);
    float inv = 1.0f / fmaxf(sqrtf(s), 1e-12f);
    float e0 = fmaxf(a0 * inv, 0.f);
    float e1 = fmaxf(a1 * inv, 0.f);
    float e2 = fmaxf(a2 * inv, 0.f);

    const size_t EMB_OFF = 0;
    const size_t LOG_OFF = (size_t)N_NODES * NHID;
    const size_t PRB_OFF = LOG_OFF + (size_t)N_NODES * NCLASS;

    out[EMB_OFF + (size_t)node * NHID + lane]      = e0;
    out[EMB_OFF + (size_t)node * NHID + lane + 32] = e1;
    out[EMB_OFF + (size_t)node * NHID + lane + 64] = e2;
    esh[wid][lane] = e0; esh[wid][lane + 32] = e1; esh[wid][lane + 64] = e2;
    __syncwarp();

    float l0 = -INFINITY, l1 = -INFINITY;
    if (lane < NCLASS) {
        float a = bs[lane];
#pragma unroll
        for (int k = 0; k < NHID; k++) a += esh[wid][k] * Ws[k * NCLASS + lane];
        l0 = a;
    }
    if (lane < NCLASS - 32) {
        float a = bs[lane + 32];
#pragma unroll
        for (int k = 0; k < NHID; k++) a += esh[wid][k] * Ws[k * NCLASS + lane + 32];
        l1 = a;
    }

    float m = fmaxf(l0, l1);
#pragma unroll
    for (int o = 16; o; o >>= 1) m = fmaxf(m, __shfl_xor_sync(0xFFFFFFFFu, m, o));
    float sum = 0.f, p0 = 0.f, p1 = 0.f;
    if (lane < NCLASS)      { p0 = expf(l0 - m); sum += p0; }
    if (lane < NCLASS - 32) { p1 = expf(l1 - m); sum += p1; }
#pragma unroll
    for (int o = 16; o; o >>= 1) sum += __shfl_xor_sync(0xFFFFFFFFu, sum, o);
    float invs = 1.0f / sum;

    if (lane < NCLASS) {
        out[LOG_OFF + (size_t)node * NCLASS + lane] = l0;
        out[PRB_OFF + (size_t)node * NCLASS + lane] = p0 * invs;
    }
    if (lane < NCLASS - 32) {
        out[LOG_OFF + (size_t)node * NCLASS + lane + 32] = l1;
        out[PRB_OFF + (size_t)node * NCLASS + lane + 32] = p1 * invs;
    }
}

// ===========================================================================
extern "C" void kernel_launch(void* const* d_in, const int* in_sizes, int n_in,
                              void* d_out, int out_size) {
    const float* x    = (const float*)d_in[0];
    const int*   ei   = (const int*)d_in[1];
    const float* ew   = (const float*)d_in[2];
    const float* W1   = (const float*)d_in[3];
    const float* b1   = (const float*)d_in[4];
    const float* W2   = (const float*)d_in[5];
    const float* b2   = (const float*)d_in[6];
    const float* W3   = (const float*)d_in[7];
    const float* b3   = (const float*)d_in[8];
    const float* linW = (const float*)d_in[9];
    const float* linb = (const float*)d_in[10];
    float* out = (float*)d_out;

    const int* src = ei;
    const int* dst = ei + N_EDGES;

    void* pa = nullptr;
    cudaGetSymbolAddress(&pa, g_a);
    const float* xa = (const float*)pa;

    const int EDGE_GRID = (N_EDGES + 255) / 256;      // 3125
    const int GEMM_GRID = (N_NODES + 63) / 64;        // 782 (64-row tiles)
    const int AGG_GRID  = (N_NODES * 32 + 255) / 256; // warp/node, 6250
    dim3 gblk(16, 16);

    // ---- CSR build, layer-1 GEMM kept in slot 3 (profiled) ----
    zero_cnt_kernel<<<NODE_BLKS, 256>>>();                 // slot 0
    hist_kernel<<<EDGE_GRID, 256>>>(dst);                  // slot 1
    scan_claim_kernel<<<NODE_BLKS, 256>>>();               // slot 2
    gemm_kernel<NFEAT><<<GEMM_GRID, gblk>>>(x, W1);        // slot 3 (profiled)
    place_kernel<<<EDGE_GRID, 256>>>(src, dst, ew);        // slot 4

    // ---- Layer 1 aggregation ----
    agg_kernel<<<AGG_GRID, 256>>>(b1);
    // ---- Layer 2 ----
    gemm_kernel<NHID><<<GEMM_GRID, gblk>>>(xa, W2);
    agg_kernel<<<AGG_GRID, 256>>>(b2);
    // ---- Layer 3 + head ----
    gemm_kernel<NHID><<<GEMM_GRID, gblk>>>(xa, W3);
    agg_head_kernel<<<(N_NODES + 7) / 8, 256>>>(b3, linW, linb, out);
}

// round 15
// speedup vs baseline: 1.0724x; 1.0724x over previous
#include <cuda_runtime.h>
#include <cuda_fp16.h>
#include <math.h>

#define N_NODES 50000
#define N_EDGES 800000
#define NFEAT   128
#define NHID    96
#define NCLASS  40
#define NODE_BLKS 196   // ceil(N_NODES/256)

// ---- static scratch (allocation-free) ----
__device__ __align__(16) __half g_h[N_NODES * NHID];  // post-GEMM features (fp16: halves gather traffic)
__device__ __align__(16) float  g_a[N_NODES * NHID];  // post-aggregation features (fp32)
__device__ int  g_cnt[N_NODES];     // degree histogram
__device__ int  g_cnt2[N_NODES];    // placement cursors
__device__ int  g_rowbeg[N_NODES];  // CSR segment base (atomic-claimed)
__device__ int  g_cursor;
__device__ __align__(16) int2 g_edges[N_EDGES];   // {src, bits(w)} compact

// ===========================================================================
// CSR build: zero -> hist -> scan+claim (1 kernel) -> place
// ===========================================================================
__global__ void zero_cnt_kernel() {
    int i = blockIdx.x * blockDim.x + threadIdx.x;
    if (i < N_NODES) { g_cnt[i] = 0; g_cnt2[i] = 0; }
    if (i == 0) g_cursor = 0;
}

__global__ void hist_kernel(const int* __restrict__ dst) {
    int e = blockIdx.x * blockDim.x + threadIdx.x;
    if (e < N_EDGES) atomicAdd(&g_cnt[dst[e]], 1);
}

// Block-local inclusive scan; block total claimed from global cursor.
__global__ void scan_claim_kernel() {
    __shared__ int sh[256];
    __shared__ int base_sh;
    int t = threadIdx.x;
    int i = blockIdx.x * 256 + t;
    int c = (i < N_NODES) ? g_cnt[i] : 0;
    sh[t] = c;
    __syncthreads();
#pragma unroll
    for (int off = 1; off < 256; off <<= 1) {
        int v = (t >= off) ? sh[t - off] : 0;
        __syncthreads();
        sh[t] += v;
        __syncthreads();
    }
    if (t == 255) base_sh = atomicAdd(&g_cursor, sh[255]);
    __syncthreads();
    if (i < N_NODES) g_rowbeg[i] = base_sh + sh[t] - c;
}

__global__ void place_kernel(const int* __restrict__ src,
                             const int* __restrict__ dst,
                             const float* __restrict__ ew) {
    int e = blockIdx.x * blockDim.x + threadIdx.x;
    if (e >= N_EDGES) return;
    int d = dst[e];
    int p = g_rowbeg[d] + atomicAdd(&g_cnt2[d], 1);
    g_edges[p] = make_int2(src[e], __float_as_int(ew[e]));
}

// ===========================================================================
// GEMM: g_h[r,c] = fp16( sum_k X[r,k]*W[k,c] ). R11 config (best measured):
// CTA tile 128x96, 256 threads (16x16), per-thread 8 rows x 6 cols,
// f32x2 packed FMA, __launch_bounds__(256,3). Epilogue converts to fp16.
// ===========================================================================
template <int K>
__global__ void __launch_bounds__(256, 3) gemm_kernel(const float* __restrict__ X,
                                                      const float* __restrict__ W) {
    __shared__ float Xs[32][132];   // [k][row], padded
    __shared__ float Ws[32][96];    // [k][col]
    int tx = threadIdx.x;           // 0..15 -> cols tx*6..tx*6+5
    int ty = threadIdx.y;           // 0..15 -> rows ty*8..ty*8+7
    int tid = ty * 16 + tx;
    int rowBase = blockIdx.x * 128;

    // acc2[i][p] = packed {col tx*6+2p, col tx*6+2p+1} for row ty*8+i
    unsigned long long acc2[8][3] = {};

    for (int kt = 0; kt < K; kt += 32) {
        for (int idx = tid; idx < 128 * 8; idx += 256) {
            int row = idx >> 3;
            int kc  = idx & 7;
            int gr = rowBase + row;
            if (gr >= N_NODES) gr = N_NODES - 1;
            float4 v = *reinterpret_cast<const float4*>(X + (size_t)gr * K + kt + kc * 4);
            Xs[kc * 4 + 0][row] = v.x;
            Xs[kc * 4 + 1][row] = v.y;
            Xs[kc * 4 + 2][row] = v.z;
            Xs[kc * 4 + 3][row] = v.w;
        }
        for (int idx = tid; idx < 32 * 24; idx += 256) {
            int kk = idx / 24;
            int cc = idx % 24;
            *reinterpret_cast<float4*>(&Ws[kk][cc * 4]) =
                *reinterpret_cast<const float4*>(W + (size_t)(kt + kk) * NHID + cc * 4);
        }
        __syncthreads();

#pragma unroll
        for (int k = 0; k < 32; k++) {
            float xr[8];
            *reinterpret_cast<float4*>(&xr[0]) = *reinterpret_cast<float4*>(&Xs[k][ty * 8]);
            *reinterpret_cast<float4*>(&xr[4]) = *reinterpret_cast<float4*>(&Xs[k][ty * 8 + 4]);
            unsigned long long wc2[3];
            wc2[0] = *reinterpret_cast<unsigned long long*>(&Ws[k][tx * 6]);
            wc2[1] = *reinterpret_cast<unsigned long long*>(&Ws[k][tx * 6 + 2]);
            wc2[2] = *reinterpret_cast<unsigned long long*>(&Ws[k][tx * 6 + 4]);
#pragma unroll
            for (int i = 0; i < 8; i++) {
                unsigned int xb = __float_as_uint(xr[i]);
                unsigned long long xs;
                asm("mov.b64 %0, {%1, %1};" : "=l"(xs) : "r"(xb));
#pragma unroll
                for (int p = 0; p < 3; p++)
                    asm("fma.rn.f32x2 %0, %1, %2, %0;"
                        : "+l"(acc2[i][p]) : "l"(xs), "l"(wc2[p]));
            }
        }
        __syncthreads();
    }

#pragma unroll
    for (int i = 0; i < 8; i++) {
        int gr = rowBase + ty * 8 + i;
        if (gr < N_NODES) {
            __half2* o = reinterpret_cast<__half2*>(g_h + (size_t)gr * NHID + tx * 6);
#pragma unroll
            for (int p = 0; p < 3; p++) {
                float2 f = *reinterpret_cast<float2*>(&acc2[i][p]);
                o[p] = __floats2half2_rn(f.x, f.y);
            }
        }
    }
}

// ===========================================================================
// Aggregation core: warp accumulates weighted fp16 rows of g_h for one node.
// 8-edge groups; tail done as one predicated 8-wide group (w=0 lanes).
// fp16 rows are 192 B -> half the L2 sector traffic of fp32.
// ===========================================================================
__device__ __forceinline__ void agg8(const int2* __restrict__ eb, int j, int cnt,
                                     bool full, int lane,
                                     float& a0, float& a1, float& a2) {
    int   srcs[8];
    float ws[8];
#pragma unroll
    for (int k = 0; k < 8; k++) {
        bool ok = full || (j + k < cnt);
        int2 e = ok ? __ldg(&eb[j + k]) : make_int2(0, 0);
        srcs[k] = e.x;
        ws[k]   = ok ? __int_as_float(e.y) : 0.f;
    }
    __half v0[8], v1[8], v2[8];
#pragma unroll
    for (int k = 0; k < 8; k++) {
        const __half* h = g_h + (size_t)srcs[k] * NHID;
        v0[k] = __ldg(h + lane);
        v1[k] = __ldg(h + lane + 32);
        v2[k] = __ldg(h + lane + 64);
    }
#pragma unroll
    for (int k = 0; k < 8; k++) {
        a0 += ws[k] * __half2float(v0[k]);
        a1 += ws[k] * __half2float(v1[k]);
        a2 += ws[k] * __half2float(v2[k]);
    }
}

__device__ __forceinline__ void agg_rows(int node, int lane,
                                         float& a0, float& a1, float& a2) {
    int beg = __ldg(&g_rowbeg[node]);
    int cnt = __ldg(&g_cnt[node]);
    const int2* eb = g_edges + beg;
    int nfull = cnt & ~7;
    for (int j = 0; j < nfull; j += 8)
        agg8(eb, j, cnt, true, lane, a0, a1, a2);
    if (cnt & 7)
        agg8(eb, nfull, cnt, false, lane, a0, a1, a2);
}

// Aggregation + bias + L2-normalize + ReLU. One warp per dst node.
__global__ void agg_kernel(const float* __restrict__ bias) {
    int gw   = (blockIdx.x * blockDim.x + threadIdx.x) >> 5;
    int lane = threadIdx.x & 31;
    if (gw >= N_NODES) return;

    float a0 = 0.f, a1 = 0.f, a2 = 0.f;
    agg_rows(gw, lane, a0, a1, a2);

    a0 += __ldg(bias + lane); a1 += __ldg(bias + lane + 32); a2 += __ldg(bias + lane + 64);
    float s = a0 * a0 + a1 * a1 + a2 * a2;
#pragma unroll
    for (int o = 16; o; o >>= 1) s += __shfl_xor_sync(0xFFFFFFFFu, s, o);
    float inv = 1.0f / fmaxf(sqrtf(s), 1e-12f);

    float* row = g_a + (size_t)gw * NHID;
    row[lane]      = fmaxf(a0 * inv, 0.f);
    row[lane + 32] = fmaxf(a1 * inv, 0.f);
    row[lane + 64] = fmaxf(a2 * inv, 0.f);
}

// ===========================================================================
// Layer 3 fused head: agg + bias + norm + relu + emb + logits + softmax.
// ===========================================================================
__global__ void agg_head_kernel(const float* __restrict__ bias,
                                const float* __restrict__ linW,
                                const float* __restrict__ linb,
                                float* __restrict__ out) {
    __shared__ float Ws[NHID * NCLASS];
    __shared__ float bs[NCLASS];
    __shared__ float esh[8][NHID];

    int tid = threadIdx.x;
    for (int i = tid; i < NHID * NCLASS; i += 256) Ws[i] = linW[i];
    if (tid < NCLASS) bs[tid] = linb[tid];
    __syncthreads();

    int wid  = tid >> 5;
    int lane = tid & 31;
    int node = blockIdx.x * 8 + wid;
    if (node >= N_NODES) return;

    float a0 = 0.f, a1 = 0.f, a2 = 0.f;
    agg_rows(node, lane, a0, a1, a2);

    a0 += __ldg(bias + lane); a1 += __ldg(bias + lane + 32); a2 += __ldg(bias + lane + 64);
    float s = a0 * a0 + a1 * a1 + a2 * a2;
#pragma unroll
    for (int o = 16; o; o >>= 1) s += __shfl_xor_sync(0xFFFFFFFFu, s, o);
    float inv = 1.0f / fmaxf(sqrtf(s), 1e-12f);
    float e0 = fmaxf(a0 * inv, 0.f);
    float e1 = fmaxf(a1 * inv, 0.f);
    float e2 = fmaxf(a2 * inv, 0.f);

    const size_t EMB_OFF = 0;
    const size_t LOG_OFF = (size_t)N_NODES * NHID;
    const size_t PRB_OFF = LOG_OFF + (size_t)N_NODES * NCLASS;

    out[EMB_OFF + (size_t)node * NHID + lane]      = e0;
    out[EMB_OFF + (size_t)node * NHID + lane + 32] = e1;
    out[EMB_OFF + (size_t)node * NHID + lane + 64] = e2;
    esh[wid][lane] = e0; esh[wid][lane + 32] = e1; esh[wid][lane + 64] = e2;
    __syncwarp();

    float l0 = -INFINITY, l1 = -INFINITY;
    if (lane < NCLASS) {
        float a = bs[lane];
#pragma unroll
        for (int k = 0; k < NHID; k++) a += esh[wid][k] * Ws[k * NCLASS + lane];
        l0 = a;
    }
    if (lane < NCLASS - 32) {
        float a = bs[lane + 32];
#pragma unroll
        for (int k = 0; k < NHID; k++) a += esh[wid][k] * Ws[k * NCLASS + lane + 32];
        l1 = a;
    }

    float m = fmaxf(l0, l1);
#pragma unroll
    for (int o = 16; o; o >>= 1) m = fmaxf(m, __shfl_xor_sync(0xFFFFFFFFu, m, o));
    float sum = 0.f, p0 = 0.f, p1 = 0.f;
    if (lane < NCLASS)      { p0 = expf(l0 - m); sum += p0; }
    if (lane < NCLASS - 32) { p1 = expf(l1 - m); sum += p1; }
#pragma unroll
    for (int o = 16; o; o >>= 1) sum += __shfl_xor_sync(0xFFFFFFFFu, sum, o);
    float invs = 1.0f / sum;

    if (lane < NCLASS) {
        out[LOG_OFF + (size_t)node * NCLASS + lane] = l0;
        out[PRB_OFF + (size_t)node * NCLASS + lane] = p0 * invs;
    }
    if (lane < NCLASS - 32) {
        out[LOG_OFF + (size_t)node * NCLASS + lane + 32] = l1;
        out[PRB_OFF + (size_t)node * NCLASS + lane + 32] = p1 * invs;
    }
}

// ===========================================================================
extern "C" void kernel_launch(void* const* d_in, const int* in_sizes, int n_in,
                              void* d_out, int out_size) {
    const float* x    = (const float*)d_in[0];
    const int*   ei   = (const int*)d_in[1];
    const float* ew   = (const float*)d_in[2];
    const float* W1   = (const float*)d_in[3];
    const float* b1   = (const float*)d_in[4];
    const float* W2   = (const float*)d_in[5];
    const float* b2   = (const float*)d_in[6];
    const float* W3   = (const float*)d_in[7];
    const float* b3   = (const float*)d_in[8];
    const float* linW = (const float*)d_in[9];
    const float* linb = (const float*)d_in[10];
    float* out = (float*)d_out;

    const int* src = ei;
    const int* dst = ei + N_EDGES;

    void* pa = nullptr;
    cudaGetSymbolAddress(&pa, g_a);
    const float* xa = (const float*)pa;

    const int EDGE_GRID = (N_EDGES + 255) / 256;      // 3125
    const int GEMM_GRID = (N_NODES + 127) / 128;      // 391 (R11 tile)
    const int AGG_GRID  = (N_NODES * 32 + 255) / 256; // warp/node, 6250
    dim3 gblk(16, 16);

    // ---- CSR build, layer-1 GEMM kept in slot 3 (profiled) ----
    zero_cnt_kernel<<<NODE_BLKS, 256>>>();                 // slot 0
    hist_kernel<<<EDGE_GRID, 256>>>(dst);                  // slot 1
    scan_claim_kernel<<<NODE_BLKS, 256>>>();               // slot 2
    gemm_kernel<NFEAT><<<GEMM_GRID, gblk>>>(x, W1);        // slot 3 (profiled)
    place_kernel<<<EDGE_GRID, 256>>>(src, dst, ew);        // slot 4

    // ---- Layer 1 aggregation ----
    agg_kernel<<<AGG_GRID, 256>>>(b1);
    // ---- Layer 2 ----
    gemm_kernel<NHID><<<GEMM_GRID, gblk>>>(xa, W2);
    agg_kernel<<<AGG_GRID, 256>>>(b2);
    // ---- Layer 3 + head ----
    gemm_kernel<NHID><<<GEMM_GRID, gblk>>>(xa, W3);
    agg_head_kernel<<<(N_NODES + 7) / 8, 256>>>(b3, linW, linb, out);
}

// round 16
// speedup vs baseline: 1.0962x; 1.0222x over previous
#include <cuda_runtime.h>
#include <cuda_fp16.h>
#include <math.h>

#define N_NODES 50000
#define N_EDGES 800000
#define NFEAT   128
#define NHID    96
#define NCLASS  40
#define NODE_BLKS 196   // ceil(N_NODES/256)

// ---- static scratch (allocation-free) ----
__device__ __align__(16) __half g_h[N_NODES * NHID];  // post-GEMM features (fp16)
__device__ __align__(16) float  g_a[N_NODES * NHID];  // post-aggregation features (fp32)
__device__ int  g_cnt[N_NODES];     // degree histogram
__device__ int  g_cnt2[N_NODES];    // placement cursors
__device__ int  g_rowbeg[N_NODES];  // CSR segment base (atomic-claimed)
__device__ int  g_cursor;
__device__ __align__(16) int2 g_edges[N_EDGES];   // {src, bits(w)} compact

// ===========================================================================
// CSR build: zero -> hist -> scan+claim (1 kernel) -> place
// ===========================================================================
__global__ void zero_cnt_kernel() {
    int i = blockIdx.x * blockDim.x + threadIdx.x;
    if (i < N_NODES) { g_cnt[i] = 0; g_cnt2[i] = 0; }
    if (i == 0) g_cursor = 0;
}

__global__ void hist_kernel(const int* __restrict__ dst) {
    int e = blockIdx.x * blockDim.x + threadIdx.x;
    if (e < N_EDGES) atomicAdd(&g_cnt[dst[e]], 1);
}

__global__ void scan_claim_kernel() {
    __shared__ int sh[256];
    __shared__ int base_sh;
    int t = threadIdx.x;
    int i = blockIdx.x * 256 + t;
    int c = (i < N_NODES) ? g_cnt[i] : 0;
    sh[t] = c;
    __syncthreads();
#pragma unroll
    for (int off = 1; off < 256; off <<= 1) {
        int v = (t >= off) ? sh[t - off] : 0;
        __syncthreads();
        sh[t] += v;
        __syncthreads();
    }
    if (t == 255) base_sh = atomicAdd(&g_cursor, sh[255]);
    __syncthreads();
    if (i < N_NODES) g_rowbeg[i] = base_sh + sh[t] - c;
}

__global__ void place_kernel(const int* __restrict__ src,
                             const int* __restrict__ dst,
                             const float* __restrict__ ew) {
    int e = blockIdx.x * blockDim.x + threadIdx.x;
    if (e >= N_EDGES) return;
    int d = dst[e];
    int p = g_rowbeg[d] + atomicAdd(&g_cnt2[d], 1);
    g_edges[p] = make_int2(src[e], __float_as_int(ew[e]));
}

// ===========================================================================
// GEMM: g_h[r,c] = fp16( sum_k X[r,k]*W[k,c] ). R11/R15 config (best):
// CTA 128x96, 256 threads, per-thread 8x6, f32x2 FMA, fp16 store epilogue.
// ===========================================================================
template <int K>
__global__ void __launch_bounds__(256, 3) gemm_kernel(const float* __restrict__ X,
                                                      const float* __restrict__ W) {
    __shared__ float Xs[32][132];
    __shared__ float Ws[32][96];
    int tx = threadIdx.x;           // 0..15 -> cols tx*6..tx*6+5
    int ty = threadIdx.y;           // 0..15 -> rows ty*8..ty*8+7
    int tid = ty * 16 + tx;
    int rowBase = blockIdx.x * 128;

    unsigned long long acc2[8][3] = {};

    for (int kt = 0; kt < K; kt += 32) {
        for (int idx = tid; idx < 128 * 8; idx += 256) {
            int row = idx >> 3;
            int kc  = idx & 7;
            int gr = rowBase + row;
            if (gr >= N_NODES) gr = N_NODES - 1;
            float4 v = *reinterpret_cast<const float4*>(X + (size_t)gr * K + kt + kc * 4);
            Xs[kc * 4 + 0][row] = v.x;
            Xs[kc * 4 + 1][row] = v.y;
            Xs[kc * 4 + 2][row] = v.z;
            Xs[kc * 4 + 3][row] = v.w;
        }
        for (int idx = tid; idx < 32 * 24; idx += 256) {
            int kk = idx / 24;
            int cc = idx % 24;
            *reinterpret_cast<float4*>(&Ws[kk][cc * 4]) =
                *reinterpret_cast<const float4*>(W + (size_t)(kt + kk) * NHID + cc * 4);
        }
        __syncthreads();

#pragma unroll
        for (int k = 0; k < 32; k++) {
            float xr[8];
            *reinterpret_cast<float4*>(&xr[0]) = *reinterpret_cast<float4*>(&Xs[k][ty * 8]);
            *reinterpret_cast<float4*>(&xr[4]) = *reinterpret_cast<float4*>(&Xs[k][ty * 8 + 4]);
            unsigned long long wc2[3];
            wc2[0] = *reinterpret_cast<unsigned long long*>(&Ws[k][tx * 6]);
            wc2[1] = *reinterpret_cast<unsigned long long*>(&Ws[k][tx * 6 + 2]);
            wc2[2] = *reinterpret_cast<unsigned long long*>(&Ws[k][tx * 6 + 4]);
#pragma unroll
            for (int i = 0; i < 8; i++) {
                unsigned int xb = __float_as_uint(xr[i]);
                unsigned long long xs;
                asm("mov.b64 %0, {%1, %1};" : "=l"(xs) : "r"(xb));
#pragma unroll
                for (int p = 0; p < 3; p++)
                    asm("fma.rn.f32x2 %0, %1, %2, %0;"
                        : "+l"(acc2[i][p]) : "l"(xs), "l"(wc2[p]));
            }
        }
        __syncthreads();
    }

#pragma unroll
    for (int i = 0; i < 8; i++) {
        int gr = rowBase + ty * 8 + i;
        if (gr < N_NODES) {
            __half2* o = reinterpret_cast<__half2*>(g_h + (size_t)gr * NHID + tx * 6);
#pragma unroll
            for (int p = 0; p < 3; p++) {
                float2 f = *reinterpret_cast<float2*>(&acc2[i][p]);
                o[p] = __floats2half2_rn(f.x, f.y);
            }
        }
    }
}

// ===========================================================================
// Aggregation core v2: ONE LDG.64 per edge. Lane l<24 owns cols [4l,4l+4)
// (8 bytes fp16). LDG/edge drops 4 -> 2 (meta + gather) vs the old
// 3-segment scalar gather; LSU floor halves (22 -> 11 us/layer).
// 8-edge groups, predicated tail (w=0).
// ===========================================================================
__device__ __forceinline__ void agg8(const int2* __restrict__ eb, int j, int cnt,
                                     bool full, int lane, bool act,
                                     float2& accA, float2& accB) {
    int   srcs[8];
    float ws[8];
#pragma unroll
    for (int k = 0; k < 8; k++) {
        bool ok = full || (j + k < cnt);
        int2 e = ok ? __ldg(&eb[j + k]) : make_int2(0, 0);
        srcs[k] = e.x;
        ws[k]   = ok ? __int_as_float(e.y) : 0.f;
    }
    uint2 v[8];
#pragma unroll
    for (int k = 0; k < 8; k++) {
        const uint2* h = reinterpret_cast<const uint2*>(g_h + (size_t)srcs[k] * NHID);
        v[k] = act ? __ldg(h + lane) : make_uint2(0u, 0u);
    }
#pragma unroll
    for (int k = 0; k < 8; k++) {
        __half2 h0 = *reinterpret_cast<__half2*>(&v[k].x);
        __half2 h1 = *reinterpret_cast<__half2*>(&v[k].y);
        float2 f0 = __half22float2(h0);
        float2 f1 = __half22float2(h1);
        accA.x += ws[k] * f0.x; accA.y += ws[k] * f0.y;
        accB.x += ws[k] * f1.x; accB.y += ws[k] * f1.y;
    }
}

__device__ __forceinline__ void agg_rows(int node, int lane, bool act,
                                         float2& accA, float2& accB) {
    int beg = __ldg(&g_rowbeg[node]);
    int cnt = __ldg(&g_cnt[node]);
    const int2* eb = g_edges + beg;
    int nfull = cnt & ~7;
    for (int j = 0; j < nfull; j += 8)
        agg8(eb, j, cnt, true, lane, act, accA, accB);
    if (cnt & 7)
        agg8(eb, nfull, cnt, false, lane, act, accA, accB);
}

// Aggregation + bias + L2-normalize + ReLU. One warp per dst node.
__global__ void agg_kernel(const float* __restrict__ bias) {
    int gw   = (blockIdx.x * blockDim.x + threadIdx.x) >> 5;
    int lane = threadIdx.x & 31;
    if (gw >= N_NODES) return;
    bool act = lane < 24;

    float2 accA = make_float2(0.f, 0.f), accB = make_float2(0.f, 0.f);
    agg_rows(gw, lane, act, accA, accB);

    if (act) {
        float4 b = __ldg(reinterpret_cast<const float4*>(bias) + lane);
        accA.x += b.x; accA.y += b.y; accB.x += b.z; accB.y += b.w;
    }
    float s = accA.x * accA.x + accA.y * accA.y + accB.x * accB.x + accB.y * accB.y;
#pragma unroll
    for (int o = 16; o; o >>= 1) s += __shfl_xor_sync(0xFFFFFFFFu, s, o);
    float inv = 1.0f / fmaxf(sqrtf(s), 1e-12f);

    if (act) {
        float4 r = make_float4(fmaxf(accA.x * inv, 0.f), fmaxf(accA.y * inv, 0.f),
                               fmaxf(accB.x * inv, 0.f), fmaxf(accB.y * inv, 0.f));
        reinterpret_cast<float4*>(g_a + (size_t)gw * NHID)[lane] = r;
    }
}

// ===========================================================================
// Layer 3 fused head: agg + bias + norm + relu + emb + logits + softmax.
// ===========================================================================
__global__ void agg_head_kernel(const float* __restrict__ bias,
                                const float* __restrict__ linW,
                                const float* __restrict__ linb,
                                float* __restrict__ out) {
    __shared__ float Ws[NHID * NCLASS];
    __shared__ float bs[NCLASS];
    __shared__ __align__(16) float esh[8][NHID];

    int tid = threadIdx.x;
    for (int i = tid; i < NHID * NCLASS; i += 256) Ws[i] = linW[i];
    if (tid < NCLASS) bs[tid] = linb[tid];
    __syncthreads();

    int wid  = tid >> 5;
    int lane = tid & 31;
    int node = blockIdx.x * 8 + wid;
    if (node >= N_NODES) return;
    bool act = lane < 24;

    float2 accA = make_float2(0.f, 0.f), accB = make_float2(0.f, 0.f);
    agg_rows(node, lane, act, accA, accB);

    if (act) {
        float4 b = __ldg(reinterpret_cast<const float4*>(bias) + lane);
        accA.x += b.x; accA.y += b.y; accB.x += b.z; accB.y += b.w;
    }
    float s = accA.x * accA.x + accA.y * accA.y + accB.x * accB.x + accB.y * accB.y;
#pragma unroll
    for (int o = 16; o; o >>= 1) s += __shfl_xor_sync(0xFFFFFFFFu, s, o);
    float inv = 1.0f / fmaxf(sqrtf(s), 1e-12f);

    const size_t EMB_OFF = 0;
    const size_t LOG_OFF = (size_t)N_NODES * NHID;
    const size_t PRB_OFF = LOG_OFF + (size_t)N_NODES * NCLASS;

    if (act) {
        float4 r = make_float4(fmaxf(accA.x * inv, 0.f), fmaxf(accA.y * inv, 0.f),
                               fmaxf(accB.x * inv, 0.f), fmaxf(accB.y * inv, 0.f));
        reinterpret_cast<float4*>(out + EMB_OFF + (size_t)node * NHID)[lane] = r;
        reinterpret_cast<float4*>(&esh[wid][0])[lane] = r;
    }
    __syncwarp();

    float l0 = -INFINITY, l1 = -INFINITY;
    if (lane < NCLASS) {
        float a = bs[lane];
#pragma unroll
        for (int k = 0; k < NHID; k++) a += esh[wid][k] * Ws[k * NCLASS + lane];
        l0 = a;
    }
    if (lane < NCLASS - 32) {
        float a = bs[lane + 32];
#pragma unroll
        for (int k = 0; k < NHID; k++) a += esh[wid][k] * Ws[k * NCLASS + lane + 32];
        l1 = a;
    }

    float m = fmaxf(l0, l1);
#pragma unroll
    for (int o = 16; o; o >>= 1) m = fmaxf(m, __shfl_xor_sync(0xFFFFFFFFu, m, o));
    float sum = 0.f, p0 = 0.f, p1 = 0.f;
    if (lane < NCLASS)      { p0 = expf(l0 - m); sum += p0; }
    if (lane < NCLASS - 32) { p1 = expf(l1 - m); sum += p1; }
#pragma unroll
    for (int o = 16; o; o >>= 1) sum += __shfl_xor_sync(0xFFFFFFFFu, sum, o);
    float invs = 1.0f / sum;

    if (lane < NCLASS) {
        out[LOG_OFF + (size_t)node * NCLASS + lane] = l0;
        out[PRB_OFF + (size_t)node * NCLASS + lane] = p0 * invs;
    }
    if (lane < NCLASS - 32) {
        out[LOG_OFF + (size_t)node * NCLASS + lane + 32] = l1;
        out[PRB_OFF + (size_t)node * NCLASS + lane + 32] = p1 * invs;
    }
}

// ===========================================================================
extern "C" void kernel_launch(void* const* d_in, const int* in_sizes, int n_in,
                              void* d_out, int out_size) {
    const float* x    = (const float*)d_in[0];
    const int*   ei   = (const int*)d_in[1];
    const float* ew   = (const float*)d_in[2];
    const float* W1   = (const float*)d_in[3];
    const float* b1   = (const float*)d_in[4];
    const float* W2   = (const float*)d_in[5];
    const float* b2   = (const float*)d_in[6];
    const float* W3   = (const float*)d_in[7];
    const float* b3   = (const float*)d_in[8];
    const float* linW = (const float*)d_in[9];
    const float* linb = (const float*)d_in[10];
    float* out = (float*)d_out;

    const int* src = ei;
    const int* dst = ei + N_EDGES;

    void* pa = nullptr;
    cudaGetSymbolAddress(&pa, g_a);
    const float* xa = (const float*)pa;

    const int EDGE_GRID = (N_EDGES + 255) / 256;      // 3125
    const int GEMM_GRID = (N_NODES + 127) / 128;      // 391
    const int AGG_GRID  = (N_NODES * 32 + 255) / 256; // warp/node, 6250
    dim3 gblk(16, 16);

    // ---- CSR build, layer-1 GEMM kept in slot 3 (profiled) ----
    zero_cnt_kernel<<<NODE_BLKS, 256>>>();                 // slot 0
    hist_kernel<<<EDGE_GRID, 256>>>(dst);                  // slot 1
    scan_claim_kernel<<<NODE_BLKS, 256>>>();               // slot 2
    gemm_kernel<NFEAT><<<GEMM_GRID, gblk>>>(x, W1);        // slot 3 (profiled)
    place_kernel<<<EDGE_GRID, 256>>>(src, dst, ew);        // slot 4

    // ---- Layer 1 aggregation ----
    agg_kernel<<<AGG_GRID, 256>>>(b1);
    // ---- Layer 2 ----
    gemm_kernel<NHID><<<GEMM_GRID, gblk>>>(xa, W2);
    agg_kernel<<<AGG_GRID, 256>>>(b2);
    // ---- Layer 3 + head ----
    gemm_kernel<NHID><<<GEMM_GRID, gblk>>>(xa, W3);
    agg_head_kernel<<<(N_NODES + 7) / 8, 256>>>(b3, linW, linb, out);
}